// round 1
// baseline (speedup 1.0000x reference)
#include <cuda_runtime.h>

// Problem constants (fixed by the dataset)
#define NN   50000
#define EE   800000
#define HD   128      // hidden = H*D = in_dim
#define OUTD 64
#define LN_EPS 1e-5f

// -------- device scratch (allocation-free rule: __device__ globals) --------
__device__ __align__(16) float g_ft[NN * HD];   // GEMM output / per-layer features
__device__ __align__(16) float g_h1[NN * HD];   // layer-0 output
__device__ __align__(16) float g_h2[NN * HD];   // layer-1 output
__device__ __align__(16) float g_el[NN * 4];
__device__ __align__(16) float g_er[NN * 4];
__device__ __align__(16) float g_att[EE * 4];   // edge scores -> attention
__device__ int g_cnt[NN];
__device__ int g_off[NN];
__device__ int g_cur[NN];
__device__ int g_csr[EE];
__device__ int g_bsum[128];

// ---------------------------- CSR build ------------------------------------
__global__ void k_zero_cnt() {
    int i = blockIdx.x * blockDim.x + threadIdx.x;
    if (i < NN) g_cnt[i] = 0;
}

__global__ void k_hist(const int* __restrict__ dst) {
    int e = blockIdx.x * blockDim.x + threadIdx.x;
    if (e < EE) atomicAdd(&g_cnt[dst[e]], 1);
}

__global__ void k_scan1() {
    __shared__ int sh[512];
    int t = threadIdx.x;
    int i = blockIdx.x * 512 + t;
    int v = (i < NN) ? g_cnt[i] : 0;
    sh[t] = v;
    __syncthreads();
    for (int off = 1; off < 512; off <<= 1) {
        int add = (t >= off) ? sh[t - off] : 0;
        __syncthreads();
        sh[t] += add;
        __syncthreads();
    }
    if (i < NN) g_off[i] = sh[t];               // inclusive scan (temp)
    if (t == 511) g_bsum[blockIdx.x] = sh[511];
}

__global__ void k_scan2(int nb) {
    __shared__ int sh[128];
    int t = threadIdx.x;
    if (t < nb) sh[t] = g_bsum[t];
    __syncthreads();
    if (t == 0) {
        int run = 0;
        for (int b = 0; b < nb; b++) { int x = sh[b]; sh[b] = run; run += x; }
    }
    __syncthreads();
    if (t < nb) g_bsum[t] = sh[t];
}

__global__ void k_scan3() {
    int t = threadIdx.x;
    int i = blockIdx.x * 512 + t;
    if (i < NN) {
        int ex = g_off[i] - g_cnt[i] + g_bsum[blockIdx.x];  // exclusive
        g_off[i] = ex;
        g_cur[i] = ex;
    }
}

__global__ void k_scatter(const int* __restrict__ dst) {
    int e = blockIdx.x * blockDim.x + threadIdx.x;
    if (e < EE) {
        int p = atomicAdd(&g_cur[dst[e]], 1);
        g_csr[p] = e;
    }
}

// ------------------------------- GEMM ---------------------------------------
// C[N, MC] = A[N,128] @ B[128, MC], fp32, 64-row tiles, BK=32.
template <int MC>
__global__ void k_gemm(const float* __restrict__ A, const float* __restrict__ B,
                       float* __restrict__ C) {
    constexpr int CPT = MC / 16;  // cols per thread (8 or 4)
    __shared__ float As[64][33];
    __shared__ float Bs[32][MC];
    int tid = threadIdx.x;
    int row0 = blockIdx.x * 64;
    int ty = tid >> 4;   // 0..15 -> 4 rows each
    int tx = tid & 15;   // col group

    float acc[4][CPT];
#pragma unroll
    for (int i = 0; i < 4; i++)
#pragma unroll
        for (int j = 0; j < CPT; j++) acc[i][j] = 0.f;

    for (int kt = 0; kt < 128; kt += 32) {
        // stage A: 64x32 floats = 512 float4, 2 per thread
#pragma unroll
        for (int i = 0; i < 2; i++) {
            int idx = tid + i * 256;
            int r = idx >> 3, c = idx & 7;
            int gr = row0 + r;
            float4 v = make_float4(0.f, 0.f, 0.f, 0.f);
            if (gr < NN) v = *(const float4*)&A[gr * 128 + kt + c * 4];
            As[r][c * 4 + 0] = v.x; As[r][c * 4 + 1] = v.y;
            As[r][c * 4 + 2] = v.z; As[r][c * 4 + 3] = v.w;
        }
        // stage B: 32 x MC
#pragma unroll
        for (int i = 0; i < MC / 32; i++) {
            int idx = tid + i * 256;
            int r = idx / (MC / 4), c = idx % (MC / 4);
            *(float4*)&Bs[r][c * 4] = *(const float4*)&B[(kt + r) * MC + c * 4];
        }
        __syncthreads();
#pragma unroll
        for (int k = 0; k < 32; k++) {
            float a[4];
#pragma unroll
            for (int i = 0; i < 4; i++) a[i] = As[ty * 4 + i][k];
#pragma unroll
            for (int j = 0; j < CPT; j++) {
                float b = Bs[k][tx * CPT + j];
#pragma unroll
                for (int i = 0; i < 4; i++) acc[i][j] = fmaf(a[i], b, acc[i][j]);
            }
        }
        __syncthreads();
    }
#pragma unroll
    for (int i = 0; i < 4; i++) {
        int r = row0 + ty * 4 + i;
        if (r < NN) {
#pragma unroll
            for (int j = 0; j < CPT; j++) C[r * MC + tx * CPT + j] = acc[i][j];
        }
    }
}

// --------------------- el/er projections (warp per node) ---------------------
template <int H_, int D_>
__global__ void k_elr(const float* __restrict__ ft, const float* __restrict__ al,
                      const float* __restrict__ ar) {
    constexpr int VEC = H_ * D_ / 32;
    constexpr int GROUP = 32 / H_;  // lanes per head
    int w = (blockIdx.x * blockDim.x + threadIdx.x) >> 5;
    int lane = threadIdx.x & 31;
    if (w >= NN) return;
    const float* f = ft + w * (H_ * D_) + lane * VEC;
    float dl = 0.f, dr = 0.f;
#pragma unroll
    for (int v = 0; v < VEC; v++) {
        float x = f[v];
        dl = fmaf(x, al[lane * VEC + v], dl);
        dr = fmaf(x, ar[lane * VEC + v], dr);
    }
#pragma unroll
    for (int off = GROUP / 2; off > 0; off >>= 1) {
        dl += __shfl_xor_sync(0xffffffffu, dl, off);
        dr += __shfl_xor_sync(0xffffffffu, dr, off);
    }
    if ((lane & (GROUP - 1)) == 0) {
        int h = lane / GROUP;
        g_el[w * H_ + h] = dl;
        g_er[w * H_ + h] = dr;
    }
}

// ------------------------ edge scores (thread per edge) ----------------------
template <int H_>
__global__ void k_edge(const int* __restrict__ src, const int* __restrict__ dst,
                       const float* __restrict__ ew, const float* __restrict__ lam) {
    int e = blockIdx.x * blockDim.x + threadIdx.x;
    if (e >= EE) return;
    int s = src[e], d = dst[e];
    float wb = lam[0] * ew[e];
#pragma unroll
    for (int h = 0; h < H_; h++) {
        float v = g_el[s * H_ + h] + g_er[d * H_ + h] + wb;
        v = v > 0.f ? v : 0.2f * v;   // leaky relu
        g_att[e * H_ + h] = v;
    }
}

// ------------------- edge softmax per dst node (warp per node) ---------------
template <int H_>
__global__ void k_softmax() {
    int w = (blockIdx.x * blockDim.x + threadIdx.x) >> 5;
    int lane = threadIdx.x & 31;
    if (w >= NN) return;
    int deg = g_cnt[w];
    if (deg == 0) return;
    int st = g_off[w];

    float mx[H_];
#pragma unroll
    for (int h = 0; h < H_; h++) mx[h] = -1e30f;
    for (int j = lane; j < deg; j += 32) {
        int e = g_csr[st + j];
#pragma unroll
        for (int h = 0; h < H_; h++) mx[h] = fmaxf(mx[h], g_att[e * H_ + h]);
    }
#pragma unroll
    for (int off = 16; off > 0; off >>= 1)
#pragma unroll
        for (int h = 0; h < H_; h++)
            mx[h] = fmaxf(mx[h], __shfl_xor_sync(0xffffffffu, mx[h], off));

    float sm[H_];
#pragma unroll
    for (int h = 0; h < H_; h++) sm[h] = 0.f;
    for (int j = lane; j < deg; j += 32) {
        int e = g_csr[st + j];
#pragma unroll
        for (int h = 0; h < H_; h++) sm[h] += __expf(g_att[e * H_ + h] - mx[h]);
    }
#pragma unroll
    for (int off = 16; off > 0; off >>= 1)
#pragma unroll
        for (int h = 0; h < H_; h++)
            sm[h] += __shfl_xor_sync(0xffffffffu, sm[h], off);

    float r[H_];
#pragma unroll
    for (int h = 0; h < H_; h++) r[h] = 1.f / sm[h];

    for (int j = lane; j < deg; j += 32) {
        int e = g_csr[st + j];
#pragma unroll
        for (int h = 0; h < H_; h++)
            g_att[e * H_ + h] = __expf(g_att[e * H_ + h] - mx[h]) * r[h];
    }
}

// ----- aggregation + ELU + LayerNorm + residual (hidden layers, H=4,D=32) ----
__global__ void k_agg_fused(const float* __restrict__ ft, const int* __restrict__ src,
                            const float* __restrict__ resid, const float* __restrict__ gamma,
                            const float* __restrict__ beta, float* __restrict__ out) {
    int w = (blockIdx.x * blockDim.x + threadIdx.x) >> 5;
    int lane = threadIdx.x & 31;
    if (w >= NN) return;
    int deg = g_cnt[w];
    int st = g_off[w];
    int hl = lane >> 3;  // head owned by this lane (cols lane*4..lane*4+3)

    float4 acc = make_float4(0.f, 0.f, 0.f, 0.f);
#pragma unroll 4
    for (int j = 0; j < deg; j++) {
        int e = g_csr[st + j];
        int s = src[e];
        float a = g_att[e * 4 + hl];
        float4 f = *(const float4*)&ft[s * 128 + lane * 4];
        acc.x = fmaf(f.x, a, acc.x);
        acc.y = fmaf(f.y, a, acc.y);
        acc.z = fmaf(f.z, a, acc.z);
        acc.w = fmaf(f.w, a, acc.w);
    }
    // ELU
    acc.x = acc.x > 0.f ? acc.x : (__expf(acc.x) - 1.f);
    acc.y = acc.y > 0.f ? acc.y : (__expf(acc.y) - 1.f);
    acc.z = acc.z > 0.f ? acc.z : (__expf(acc.z) - 1.f);
    acc.w = acc.w > 0.f ? acc.w : (__expf(acc.w) - 1.f);
    // LayerNorm over 128 values (warp-wide)
    float s1 = acc.x + acc.y + acc.z + acc.w;
    float s2 = acc.x * acc.x + acc.y * acc.y + acc.z * acc.z + acc.w * acc.w;
#pragma unroll
    for (int off = 16; off > 0; off >>= 1) {
        s1 += __shfl_xor_sync(0xffffffffu, s1, off);
        s2 += __shfl_xor_sync(0xffffffffu, s2, off);
    }
    float mu = s1 * (1.f / 128.f);
    float var = s2 * (1.f / 128.f) - mu * mu;
    float rs = rsqrtf(fmaxf(var, 0.f) + LN_EPS);
    float4 g4 = *(const float4*)&gamma[lane * 4];
    float4 b4 = *(const float4*)&beta[lane * 4];
    float4 r4 = *(const float4*)&resid[w * 128 + lane * 4];
    float4 o;
    o.x = (acc.x - mu) * rs * g4.x + b4.x + r4.x;
    o.y = (acc.y - mu) * rs * g4.y + b4.y + r4.y;
    o.z = (acc.z - mu) * rs * g4.z + b4.z + r4.z;
    o.w = (acc.w - mu) * rs * g4.w + b4.w + r4.w;
    *(float4*)&out[w * 128 + lane * 4] = o;
}

// ---------------- final layer aggregation (H=1, OUT=64), dual write ----------
__global__ void k_agg_out(const float* __restrict__ ft, const int* __restrict__ src,
                          float* __restrict__ out, float* __restrict__ out2) {
    int w = (blockIdx.x * blockDim.x + threadIdx.x) >> 5;
    int lane = threadIdx.x & 31;
    if (w >= NN) return;
    int deg = g_cnt[w];
    int st = g_off[w];
    float2 acc = make_float2(0.f, 0.f);
#pragma unroll 4
    for (int j = 0; j < deg; j++) {
        int e = g_csr[st + j];
        int s = src[e];
        float a = g_att[e];
        float2 f = *(const float2*)&ft[s * 64 + lane * 2];
        acc.x = fmaf(f.x, a, acc.x);
        acc.y = fmaf(f.y, a, acc.y);
    }
    *(float2*)&out[w * 64 + lane * 2] = acc;
    if (out2) *(float2*)&out2[w * 64 + lane * 2] = acc;
}

// ------------------------------- launch --------------------------------------
extern "C" void kernel_launch(void* const* d_in, const int* in_sizes, int n_in,
                              void* d_out, int out_size) {
    (void)in_sizes; (void)n_in;
    const float* feat = (const float*)d_in[0];
    const float* ew   = (const float*)d_in[1];
    const int*   src  = (const int*)d_in[2];
    const int*   dst  = (const int*)d_in[3];
    const float* W0   = (const float*)d_in[4];
    const float* al0  = (const float*)d_in[5];
    const float* ar0  = (const float*)d_in[6];
    const float* lam0 = (const float*)d_in[7];
    const float* W1   = (const float*)d_in[8];
    const float* al1  = (const float*)d_in[9];
    const float* ar1  = (const float*)d_in[10];
    const float* lam1 = (const float*)d_in[11];
    const float* W2   = (const float*)d_in[12];
    const float* al2  = (const float*)d_in[13];
    const float* ar2  = (const float*)d_in[14];
    const float* lam2 = (const float*)d_in[15];
    const float* g0   = (const float*)d_in[16];
    const float* b0   = (const float*)d_in[17];
    const float* g1   = (const float*)d_in[18];
    const float* b1   = (const float*)d_in[19];

    float* out = (float*)d_out;
    float* out2 = (out_size >= 2 * NN * OUTD) ? out + NN * OUTD : nullptr;

    float *ftp = nullptr, *h1p = nullptr, *h2p = nullptr;
    cudaGetSymbolAddress((void**)&ftp, g_ft);
    cudaGetSymbolAddress((void**)&h1p, g_h1);
    cudaGetSymbolAddress((void**)&h2p, g_h2);

    const int eb = (EE + 255) / 256;
    const int nb512 = (NN + 511) / 512;
    const int nwb = (NN + 7) / 8;          // warp-per-node kernels, 256 thr
    const int gemmb = (NN + 63) / 64;

    // CSR by dst (recomputed every call; deterministic work)
    k_zero_cnt<<<(NN + 255) / 256, 256>>>();
    k_hist<<<eb, 256>>>(dst);
    k_scan1<<<nb512, 512>>>();
    k_scan2<<<1, 128>>>(nb512);
    k_scan3<<<nb512, 512>>>();
    k_scatter<<<eb, 256>>>(dst);

    // ----- layer 0 -----
    k_gemm<128><<<gemmb, 256>>>(feat, W0, ftp);
    k_elr<4, 32><<<nwb, 256>>>(ftp, al0, ar0);
    k_edge<4><<<eb, 256>>>(src, dst, ew, lam0);
    k_softmax<4><<<nwb, 256>>>();
    k_agg_fused<<<nwb, 256>>>(ftp, src, feat, g0, b0, h1p);

    // ----- layer 1 -----
    k_gemm<128><<<gemmb, 256>>>(h1p, W1, ftp);
    k_elr<4, 32><<<nwb, 256>>>(ftp, al1, ar1);
    k_edge<4><<<eb, 256>>>(src, dst, ew, lam1);
    k_softmax<4><<<nwb, 256>>>();
    k_agg_fused<<<nwb, 256>>>(ftp, src, h1p, g1, b1, h2p);

    // ----- layer 2 (single head, OUT=64, no activation/LN) -----
    k_gemm<64><<<gemmb, 256>>>(h2p, W2, ftp);
    k_elr<1, 64><<<nwb, 256>>>(ftp, al2, ar2);
    k_edge<1><<<eb, 256>>>(src, dst, ew, lam2);
    k_softmax<1><<<nwb, 256>>>();
    k_agg_out<<<nwb, 256>>>(ftp, src, out, out2);
}

// round 2
// speedup vs baseline: 2.1646x; 2.1646x over previous
#include <cuda_runtime.h>

#define NN   50000
#define EE   800000
#define HD   128
#define OUTD 64
#define LN_EPS 1e-5f

// -------- device scratch --------
__device__ __align__(16) float g_ft[NN * HD];
__device__ __align__(16) float g_h1[NN * HD];
__device__ __align__(16) float g_h2[NN * HD];
__device__ __align__(16) float g_el[NN * 4];
__device__ __align__(16) float g_er[NN * 4];
__device__ __align__(16) float g_att[EE * 4];   // CSR-position ordered
__device__ __align__(16) float g_cew[EE];       // edge weight in CSR order
__device__ int g_csrc[EE];                      // src node in CSR order
__device__ int g_cnt[NN];
__device__ int g_off[NN];
__device__ int g_cur[NN];
__device__ int g_bsum[128];

// ---------------------------- CSR build ------------------------------------
__global__ void k_zero_cnt() {
    int i = blockIdx.x * blockDim.x + threadIdx.x;
    if (i < NN) g_cnt[i] = 0;
}

__global__ void k_hist(const int* __restrict__ dst) {
    int e = blockIdx.x * blockDim.x + threadIdx.x;
    if (e < EE) atomicAdd(&g_cnt[dst[e]], 1);
}

__global__ void k_scan1() {
    __shared__ int sh[512];
    int t = threadIdx.x;
    int i = blockIdx.x * 512 + t;
    int v = (i < NN) ? g_cnt[i] : 0;
    sh[t] = v;
    __syncthreads();
    for (int off = 1; off < 512; off <<= 1) {
        int add = (t >= off) ? sh[t - off] : 0;
        __syncthreads();
        sh[t] += add;
        __syncthreads();
    }
    if (i < NN) g_off[i] = sh[t];
    if (t == 511) g_bsum[blockIdx.x] = sh[511];
}

__global__ void k_scan2(int nb) {
    __shared__ int sh[128];
    int t = threadIdx.x;
    if (t < nb) sh[t] = g_bsum[t];
    __syncthreads();
    if (t == 0) {
        int run = 0;
        for (int b = 0; b < nb; b++) { int x = sh[b]; sh[b] = run; run += x; }
    }
    __syncthreads();
    if (t < nb) g_bsum[t] = sh[t];
}

__global__ void k_scan3() {
    int t = threadIdx.x;
    int i = blockIdx.x * 512 + t;
    if (i < NN) {
        int ex = g_off[i] - g_cnt[i] + g_bsum[blockIdx.x];
        g_off[i] = ex;
        g_cur[i] = ex;
    }
}

__global__ void k_scatter(const int* __restrict__ src, const int* __restrict__ dst,
                          const float* __restrict__ ew) {
    int e = blockIdx.x * blockDim.x + threadIdx.x;
    if (e < EE) {
        int p = atomicAdd(&g_cur[dst[e]], 1);
        g_csrc[p] = src[e];
        g_cew[p] = ew[e];
    }
}

// ------------------------------- GEMM + fused el/er --------------------------
// C[N, MC] = A[N,128] @ B[128, MC]; epilogue reduces C rows against al/ar.
template <int MC, int H_>
__global__ void k_gemm(const float* __restrict__ A, const float* __restrict__ B,
                       float* __restrict__ C, const float* __restrict__ al,
                       const float* __restrict__ ar) {
    constexpr int CPT = MC / 16;  // 8 or 4
    __shared__ float As[64][33];
    __shared__ float Bs[32][MC];
    int tid = threadIdx.x;
    int row0 = blockIdx.x * 64;
    int ty = tid >> 4;
    int tx = tid & 15;

    float acc[4][CPT];
#pragma unroll
    for (int i = 0; i < 4; i++)
#pragma unroll
        for (int j = 0; j < CPT; j++) acc[i][j] = 0.f;

    for (int kt = 0; kt < 128; kt += 32) {
#pragma unroll
        for (int i = 0; i < 2; i++) {
            int idx = tid + i * 256;
            int r = idx >> 3, c = idx & 7;
            int gr = row0 + r;
            float4 v = make_float4(0.f, 0.f, 0.f, 0.f);
            if (gr < NN) v = *(const float4*)&A[gr * 128 + kt + c * 4];
            As[r][c * 4 + 0] = v.x; As[r][c * 4 + 1] = v.y;
            As[r][c * 4 + 2] = v.z; As[r][c * 4 + 3] = v.w;
        }
#pragma unroll
        for (int i = 0; i < MC / 32; i++) {
            int idx = tid + i * 256;
            int r = idx / (MC / 4), c = idx % (MC / 4);
            *(float4*)&Bs[r][c * 4] = *(const float4*)&B[(kt + r) * MC + c * 4];
        }
        __syncthreads();
#pragma unroll
        for (int k = 0; k < 32; k++) {
            float a[4];
#pragma unroll
            for (int i = 0; i < 4; i++) a[i] = As[ty * 4 + i][k];
#pragma unroll
            for (int j = 0; j < CPT; j++) {
                float b = Bs[k][tx * CPT + j];
#pragma unroll
                for (int i = 0; i < 4; i++) acc[i][j] = fmaf(a[i], b, acc[i][j]);
            }
        }
        __syncthreads();
    }

    // write C
#pragma unroll
    for (int i = 0; i < 4; i++) {
        int r = row0 + ty * 4 + i;
        if (r < NN) {
#pragma unroll
            for (int j = 0; j < CPT; j += 4)
                *(float4*)&C[r * MC + tx * CPT + j] =
                    make_float4(acc[i][j], acc[i][j + 1], acc[i][j + 2], acc[i][j + 3]);
        }
    }

    // fused el/er: dl[i] = sum_cols acc[i][*] * al[col], per head
    float dl[4], dr[4];
#pragma unroll
    for (int i = 0; i < 4; i++) { dl[i] = 0.f; dr[i] = 0.f; }
#pragma unroll
    for (int j = 0; j < CPT; j++) {
        float a_ = al[tx * CPT + j];
        float r_ = ar[tx * CPT + j];
#pragma unroll
        for (int i = 0; i < 4; i++) {
            dl[i] = fmaf(acc[i][j], a_, dl[i]);
            dr[i] = fmaf(acc[i][j], r_, dr[i]);
        }
    }
    if (H_ == 4) {
        // head h covers tx in [4h, 4h+4); lanes aligned mod 4 -> shfl groups
#pragma unroll
        for (int off = 1; off < 4; off <<= 1)
#pragma unroll
            for (int i = 0; i < 4; i++) {
                dl[i] += __shfl_xor_sync(0xffffffffu, dl[i], off);
                dr[i] += __shfl_xor_sync(0xffffffffu, dr[i], off);
            }
        if ((tx & 3) == 0) {
            int h = tx >> 2;
#pragma unroll
            for (int i = 0; i < 4; i++) {
                int r = row0 + ty * 4 + i;
                if (r < NN) { g_el[r * 4 + h] = dl[i]; g_er[r * 4 + h] = dr[i]; }
            }
        }
    } else {
        // single head over all 16 tx lanes (half-warp aligned)
#pragma unroll
        for (int off = 1; off < 16; off <<= 1)
#pragma unroll
            for (int i = 0; i < 4; i++) {
                dl[i] += __shfl_xor_sync(0xffffffffu, dl[i], off);
                dr[i] += __shfl_xor_sync(0xffffffffu, dr[i], off);
            }
        if (tx == 0) {
#pragma unroll
            for (int i = 0; i < 4; i++) {
                int r = row0 + ty * 4 + i;
                if (r < NN) { g_el[r] = dl[i]; g_er[r] = dr[i]; }
            }
        }
    }
}

// ---- mega kernel, hidden layers (H=4,D=32): scores+softmax+agg+ELU+LN+res ----
__global__ void k_mega4(const float* __restrict__ ft, const float* __restrict__ lam,
                        const float* __restrict__ resid, const float* __restrict__ gamma,
                        const float* __restrict__ beta, float* __restrict__ out) {
    int w = (blockIdx.x * blockDim.x + threadIdx.x) >> 5;
    int lane = threadIdx.x & 31;
    if (w >= NN) return;
    int deg = g_cnt[w];
    int st = g_off[w];
    float lamv = lam[0];
    float4 er4 = *(const float4*)&g_er[w * 4];

    // pass 1: raw scores + running max
    float4 mx = make_float4(-1e30f, -1e30f, -1e30f, -1e30f);
    for (int j = lane; j < deg; j += 32) {
        int p = st + j;
        int s = g_csrc[p];
        float wb = lamv * g_cew[p];
        float4 elv = *(const float4*)&g_el[s * 4];
        float4 sc;
        sc.x = elv.x + er4.x + wb; sc.x = sc.x > 0.f ? sc.x : 0.2f * sc.x;
        sc.y = elv.y + er4.y + wb; sc.y = sc.y > 0.f ? sc.y : 0.2f * sc.y;
        sc.z = elv.z + er4.z + wb; sc.z = sc.z > 0.f ? sc.z : 0.2f * sc.z;
        sc.w = elv.w + er4.w + wb; sc.w = sc.w > 0.f ? sc.w : 0.2f * sc.w;
        *(float4*)&g_att[p * 4] = sc;
        mx.x = fmaxf(mx.x, sc.x); mx.y = fmaxf(mx.y, sc.y);
        mx.z = fmaxf(mx.z, sc.z); mx.w = fmaxf(mx.w, sc.w);
    }
#pragma unroll
    for (int off = 16; off > 0; off >>= 1) {
        mx.x = fmaxf(mx.x, __shfl_xor_sync(0xffffffffu, mx.x, off));
        mx.y = fmaxf(mx.y, __shfl_xor_sync(0xffffffffu, mx.y, off));
        mx.z = fmaxf(mx.z, __shfl_xor_sync(0xffffffffu, mx.z, off));
        mx.w = fmaxf(mx.w, __shfl_xor_sync(0xffffffffu, mx.w, off));
    }

    // pass 2: exp (stored unnormalized) + sum
    float4 sm = make_float4(0.f, 0.f, 0.f, 0.f);
    for (int j = lane; j < deg; j += 32) {
        int p = st + j;
        float4 v = *(const float4*)&g_att[p * 4];
        v.x = __expf(v.x - mx.x); v.y = __expf(v.y - mx.y);
        v.z = __expf(v.z - mx.z); v.w = __expf(v.w - mx.w);
        *(float4*)&g_att[p * 4] = v;
        sm.x += v.x; sm.y += v.y; sm.z += v.z; sm.w += v.w;
    }
#pragma unroll
    for (int off = 16; off > 0; off >>= 1) {
        sm.x += __shfl_xor_sync(0xffffffffu, sm.x, off);
        sm.y += __shfl_xor_sync(0xffffffffu, sm.y, off);
        sm.z += __shfl_xor_sync(0xffffffffu, sm.z, off);
        sm.w += __shfl_xor_sync(0xffffffffu, sm.w, off);
    }
    int hl = lane >> 3;
    float rh = (hl == 0) ? sm.x : (hl == 1) ? sm.y : (hl == 2) ? sm.z : sm.w;
    rh = 1.f / rh;
    __syncwarp();

    // pass 3: gather-aggregate
    float4 acc = make_float4(0.f, 0.f, 0.f, 0.f);
    for (int j = 0; j < deg; j++) {
        int p = st + j;
        int s = g_csrc[p];
        float a = g_att[p * 4 + hl] * rh;
        float4 f = *(const float4*)&ft[s * 128 + lane * 4];
        acc.x = fmaf(f.x, a, acc.x);
        acc.y = fmaf(f.y, a, acc.y);
        acc.z = fmaf(f.z, a, acc.z);
        acc.w = fmaf(f.w, a, acc.w);
    }
    // ELU
    acc.x = acc.x > 0.f ? acc.x : (__expf(acc.x) - 1.f);
    acc.y = acc.y > 0.f ? acc.y : (__expf(acc.y) - 1.f);
    acc.z = acc.z > 0.f ? acc.z : (__expf(acc.z) - 1.f);
    acc.w = acc.w > 0.f ? acc.w : (__expf(acc.w) - 1.f);
    // LayerNorm over 128 (warp-wide)
    float s1 = acc.x + acc.y + acc.z + acc.w;
    float s2 = acc.x * acc.x + acc.y * acc.y + acc.z * acc.z + acc.w * acc.w;
#pragma unroll
    for (int off = 16; off > 0; off >>= 1) {
        s1 += __shfl_xor_sync(0xffffffffu, s1, off);
        s2 += __shfl_xor_sync(0xffffffffu, s2, off);
    }
    float mu = s1 * (1.f / 128.f);
    float var = s2 * (1.f / 128.f) - mu * mu;
    float rs = rsqrtf(fmaxf(var, 0.f) + LN_EPS);
    float4 g4 = *(const float4*)&gamma[lane * 4];
    float4 b4 = *(const float4*)&beta[lane * 4];
    float4 r4 = *(const float4*)&resid[w * 128 + lane * 4];
    float4 o;
    o.x = (acc.x - mu) * rs * g4.x + b4.x + r4.x;
    o.y = (acc.y - mu) * rs * g4.y + b4.y + r4.y;
    o.z = (acc.z - mu) * rs * g4.z + b4.z + r4.z;
    o.w = (acc.w - mu) * rs * g4.w + b4.w + r4.w;
    *(float4*)&out[w * 128 + lane * 4] = o;
}

// ---- mega kernel, final layer (H=1, OUT=64), dual output write --------------
__global__ void k_mega1(const float* __restrict__ ft, const float* __restrict__ lam,
                        float* __restrict__ out, float* __restrict__ out2) {
    int w = (blockIdx.x * blockDim.x + threadIdx.x) >> 5;
    int lane = threadIdx.x & 31;
    if (w >= NN) return;
    int deg = g_cnt[w];
    int st = g_off[w];
    float lamv = lam[0];
    float er = g_er[w];

    float mx = -1e30f;
    for (int j = lane; j < deg; j += 32) {
        int p = st + j;
        float sc = g_el[g_csrc[p]] + er + lamv * g_cew[p];
        sc = sc > 0.f ? sc : 0.2f * sc;
        g_att[p] = sc;
        mx = fmaxf(mx, sc);
    }
#pragma unroll
    for (int off = 16; off > 0; off >>= 1)
        mx = fmaxf(mx, __shfl_xor_sync(0xffffffffu, mx, off));

    float sm = 0.f;
    for (int j = lane; j < deg; j += 32) {
        int p = st + j;
        float v = __expf(g_att[p] - mx);
        g_att[p] = v;
        sm += v;
    }
#pragma unroll
    for (int off = 16; off > 0; off >>= 1)
        sm += __shfl_xor_sync(0xffffffffu, sm, off);
    float rinv = 1.f / sm;
    __syncwarp();

    float2 acc = make_float2(0.f, 0.f);
    for (int j = 0; j < deg; j++) {
        int p = st + j;
        int s = g_csrc[p];
        float a = g_att[p] * rinv;
        float2 f = *(const float2*)&ft[s * 64 + lane * 2];
        acc.x = fmaf(f.x, a, acc.x);
        acc.y = fmaf(f.y, a, acc.y);
    }
    *(float2*)&out[w * 64 + lane * 2] = acc;
    if (out2) *(float2*)&out2[w * 64 + lane * 2] = acc;
}

// ------------------------------- launch --------------------------------------
extern "C" void kernel_launch(void* const* d_in, const int* in_sizes, int n_in,
                              void* d_out, int out_size) {
    (void)in_sizes; (void)n_in;
    const float* feat = (const float*)d_in[0];
    const float* ew   = (const float*)d_in[1];
    const int*   src  = (const int*)d_in[2];
    const int*   dst  = (const int*)d_in[3];
    const float* W0   = (const float*)d_in[4];
    const float* al0  = (const float*)d_in[5];
    const float* ar0  = (const float*)d_in[6];
    const float* lam0 = (const float*)d_in[7];
    const float* W1   = (const float*)d_in[8];
    const float* al1  = (const float*)d_in[9];
    const float* ar1  = (const float*)d_in[10];
    const float* lam1 = (const float*)d_in[11];
    const float* W2   = (const float*)d_in[12];
    const float* al2  = (const float*)d_in[13];
    const float* ar2  = (const float*)d_in[14];
    const float* lam2 = (const float*)d_in[15];
    const float* g0   = (const float*)d_in[16];
    const float* b0   = (const float*)d_in[17];
    const float* g1   = (const float*)d_in[18];
    const float* b1   = (const float*)d_in[19];

    float* out = (float*)d_out;
    float* out2 = (out_size >= 2 * NN * OUTD) ? out + NN * OUTD : nullptr;

    float *ftp = nullptr, *h1p = nullptr, *h2p = nullptr;
    cudaGetSymbolAddress((void**)&ftp, g_ft);
    cudaGetSymbolAddress((void**)&h1p, g_h1);
    cudaGetSymbolAddress((void**)&h2p, g_h2);

    const int eb = (EE + 255) / 256;
    const int nb512 = (NN + 511) / 512;
    const int nwb = (NN + 7) / 8;
    const int gemmb = (NN + 63) / 64;

    // CSR by dst
    k_zero_cnt<<<(NN + 255) / 256, 256>>>();
    k_hist<<<eb, 256>>>(dst);
    k_scan1<<<nb512, 512>>>();
    k_scan2<<<1, 128>>>(nb512);
    k_scan3<<<nb512, 512>>>();
    k_scatter<<<eb, 256>>>(src, dst, ew);

    // layer 0
    k_gemm<128, 4><<<gemmb, 256>>>(feat, W0, ftp, al0, ar0);
    k_mega4<<<nwb, 256>>>(ftp, lam0, feat, g0, b0, h1p);

    // layer 1
    k_gemm<128, 4><<<gemmb, 256>>>(h1p, W1, ftp, al1, ar1);
    k_mega4<<<nwb, 256>>>(ftp, lam1, h1p, g1, b1, h2p);

    // layer 2
    k_gemm<64, 1><<<gemmb, 256>>>(h2p, W2, ftp, al2, ar2);
    k_mega1<<<nwb, 256>>>(ftp, lam2, out, out2);
}

// round 3
// speedup vs baseline: 2.8192x; 1.3024x over previous
#include <cuda_runtime.h>
#include <cstdint>

#define NN   50000
#define EE   800000
#define HD   128
#define OUTD 64
#define LN_EPS 1e-5f

// -------- device scratch --------
__device__ __align__(16) float g_ft[NN * HD];
__device__ __align__(16) float g_h1[NN * HD];
__device__ __align__(16) float g_h2[NN * HD];
__device__ __align__(16) float g_el[NN * 4];
__device__ __align__(16) float g_er[NN * 4];
__device__ __align__(16) float g_att[EE * 4];   // CSR-position ordered
__device__ __align__(16) float g_cew[EE];       // edge weight in CSR order
__device__ int g_csrc[EE];                      // src node in CSR order
__device__ int g_cnt[NN];
__device__ int g_off[NN];
__device__ int g_cur[NN];
__device__ int g_bsum[128];

// ---------------------------- CSR build ------------------------------------
__global__ void k_zero_cnt() {
    int i = blockIdx.x * blockDim.x + threadIdx.x;
    if (i < NN) g_cnt[i] = 0;
}

__global__ void k_hist(const int* __restrict__ dst) {
    int e = blockIdx.x * blockDim.x + threadIdx.x;
    if (e < EE) atomicAdd(&g_cnt[dst[e]], 1);
}

__global__ void k_scan1() {
    __shared__ int sh[512];
    int t = threadIdx.x;
    int i = blockIdx.x * 512 + t;
    int v = (i < NN) ? g_cnt[i] : 0;
    sh[t] = v;
    __syncthreads();
    for (int off = 1; off < 512; off <<= 1) {
        int add = (t >= off) ? sh[t - off] : 0;
        __syncthreads();
        sh[t] += add;
        __syncthreads();
    }
    if (i < NN) g_off[i] = sh[t];
    if (t == 511) g_bsum[blockIdx.x] = sh[511];
}

__global__ void k_scan2(int nb) {
    __shared__ int sh[128];
    int t = threadIdx.x;
    int v = (t < nb) ? g_bsum[t] : 0;
    sh[t] = v;
    __syncthreads();
    for (int off = 1; off < 128; off <<= 1) {
        int add = (t >= off) ? sh[t - off] : 0;
        __syncthreads();
        sh[t] += add;
        __syncthreads();
    }
    if (t < nb) g_bsum[t] = sh[t] - v;   // exclusive
}

__global__ void k_scan3() {
    int t = threadIdx.x;
    int i = blockIdx.x * 512 + t;
    if (i < NN) {
        int ex = g_off[i] - g_cnt[i] + g_bsum[blockIdx.x];
        g_off[i] = ex;
        g_cur[i] = ex;
    }
}

__global__ void k_scatter(const int* __restrict__ src, const int* __restrict__ dst,
                          const float* __restrict__ ew) {
    int e = blockIdx.x * blockDim.x + threadIdx.x;
    if (e < EE) {
        int p = atomicAdd(&g_cur[dst[e]], 1);
        g_csrc[p] = src[e];
        g_cew[p] = ew[e];
    }
}

// --------------------------- tf32 helpers ------------------------------------
__device__ __forceinline__ uint32_t f2tf32(float x) {
    uint32_t r;
    asm("cvt.rna.tf32.f32 %0, %1;" : "=r"(r) : "f"(x));
    return r;
}

// --------------------- tf32 tensor-core GEMM ---------------------------------
// C[NN, MC] = A[NN,128] @ B[128, MC].  256 threads = 8 warps, warp tile 16x64.
// MC=128 -> BM=64 (warps 4x2); MC=64 -> BM=128 (warps 8x1).
template <int MC>
__global__ void k_gemm_tf32(const float* __restrict__ A, const float* __restrict__ B,
                            float* __restrict__ C) {
    constexpr int BM = (MC == 128) ? 64 : 128;
    constexpr int BSTR = MC + 8;               // (8k+n)%32 bank permutation
    constexpr int WCOLS = MC / 64;             // 2 or 1
    constexpr int WROWS = 8 / WCOLS;           // 4 or 8
    __shared__ uint32_t As[BM][36];
    __shared__ uint32_t Bs[32][BSTR];

    int tid = threadIdx.x;
    int wid = tid >> 5, lane = tid & 31;
    int wr = wid % WROWS, wc = wid / WROWS;
    int row0 = blockIdx.x * BM;

    float c[8][4];
#pragma unroll
    for (int t = 0; t < 8; t++)
#pragma unroll
        for (int i = 0; i < 4; i++) c[t][i] = 0.f;

    for (int kt = 0; kt < 128; kt += 32) {
        // stage A (convert to tf32)
#pragma unroll
        for (int i = 0; i < BM / 32; i++) {
            int idx = tid + i * 256;
            int r = idx >> 3, cc = idx & 7;
            int gr = row0 + r;
            float4 v = make_float4(0.f, 0.f, 0.f, 0.f);
            if (gr < NN) v = *(const float4*)&A[gr * 128 + kt + cc * 4];
            As[r][cc * 4 + 0] = f2tf32(v.x);
            As[r][cc * 4 + 1] = f2tf32(v.y);
            As[r][cc * 4 + 2] = f2tf32(v.z);
            As[r][cc * 4 + 3] = f2tf32(v.w);
        }
        // stage B (convert to tf32)
#pragma unroll
        for (int i = 0; i < MC / 32; i++) {
            int idx = tid + i * 256;
            int r = idx / (MC / 4), cc = idx % (MC / 4);
            float4 v = *(const float4*)&B[(kt + r) * MC + cc * 4];
            Bs[r][cc * 4 + 0] = f2tf32(v.x);
            Bs[r][cc * 4 + 1] = f2tf32(v.y);
            Bs[r][cc * 4 + 2] = f2tf32(v.z);
            Bs[r][cc * 4 + 3] = f2tf32(v.w);
        }
        __syncthreads();
#pragma unroll
        for (int ks = 0; ks < 4; ks++) {
            int k0 = ks * 8;
            int ar = wr * 16 + (lane >> 2);
            int ac = k0 + (lane & 3);
            uint32_t a0 = As[ar][ac];
            uint32_t a1 = As[ar + 8][ac];
            uint32_t a2 = As[ar][ac + 4];
            uint32_t a3 = As[ar + 8][ac + 4];
#pragma unroll
            for (int t = 0; t < 8; t++) {
                int n0 = wc * 64 + t * 8 + (lane >> 2);
                uint32_t b0 = Bs[k0 + (lane & 3)][n0];
                uint32_t b1 = Bs[k0 + (lane & 3) + 4][n0];
                asm volatile(
                    "mma.sync.aligned.m16n8k8.row.col.f32.tf32.tf32.f32 "
                    "{%0,%1,%2,%3}, {%4,%5,%6,%7}, {%8,%9}, {%0,%1,%2,%3};"
                    : "+f"(c[t][0]), "+f"(c[t][1]), "+f"(c[t][2]), "+f"(c[t][3])
                    : "r"(a0), "r"(a1), "r"(a2), "r"(a3), "r"(b0), "r"(b1));
            }
        }
        __syncthreads();
    }
    // writeout
    int rbase = row0 + wr * 16 + (lane >> 2);
#pragma unroll
    for (int t = 0; t < 8; t++) {
        int n0 = wc * 64 + t * 8 + 2 * (lane & 3);
        if (rbase < NN)
            *(float2*)&C[rbase * MC + n0] = make_float2(c[t][0], c[t][1]);
        if (rbase + 8 < NN)
            *(float2*)&C[(rbase + 8) * MC + n0] = make_float2(c[t][2], c[t][3]);
    }
}

// --------------------- el/er projections (warp per node) ---------------------
template <int H_, int D_>
__global__ void k_elr(const float* __restrict__ ft, const float* __restrict__ al,
                      const float* __restrict__ ar) {
    constexpr int VEC = H_ * D_ / 32;
    constexpr int GROUP = 32 / H_;
    int w = (blockIdx.x * blockDim.x + threadIdx.x) >> 5;
    int lane = threadIdx.x & 31;
    if (w >= NN) return;
    const float* f = ft + w * (H_ * D_) + lane * VEC;
    float dl = 0.f, dr = 0.f;
#pragma unroll
    for (int v = 0; v < VEC; v++) {
        float x = f[v];
        dl = fmaf(x, al[lane * VEC + v], dl);
        dr = fmaf(x, ar[lane * VEC + v], dr);
    }
#pragma unroll
    for (int off = GROUP / 2; off > 0; off >>= 1) {
        dl += __shfl_xor_sync(0xffffffffu, dl, off);
        dr += __shfl_xor_sync(0xffffffffu, dr, off);
    }
    if ((lane & (GROUP - 1)) == 0) {
        int h = lane / GROUP;
        g_el[w * H_ + h] = dl;
        g_er[w * H_ + h] = dr;
    }
}

// ---- mega kernel, hidden layers (H=4,D=32): scores+softmax+agg+ELU+LN+res ----
__global__ void k_mega4(const float* __restrict__ ft, const float* __restrict__ lam,
                        const float* __restrict__ resid, const float* __restrict__ gamma,
                        const float* __restrict__ beta, float* __restrict__ out) {
    int w = (blockIdx.x * blockDim.x + threadIdx.x) >> 5;
    int lane = threadIdx.x & 31;
    if (w >= NN) return;
    int deg = g_cnt[w];
    int st = g_off[w];
    float lamv = lam[0];
    float4 er4 = *(const float4*)&g_er[w * 4];

    float4 mx = make_float4(-1e30f, -1e30f, -1e30f, -1e30f);
    for (int j = lane; j < deg; j += 32) {
        int p = st + j;
        int s = g_csrc[p];
        float wb = lamv * g_cew[p];
        float4 elv = *(const float4*)&g_el[s * 4];
        float4 sc;
        sc.x = elv.x + er4.x + wb; sc.x = sc.x > 0.f ? sc.x : 0.2f * sc.x;
        sc.y = elv.y + er4.y + wb; sc.y = sc.y > 0.f ? sc.y : 0.2f * sc.y;
        sc.z = elv.z + er4.z + wb; sc.z = sc.z > 0.f ? sc.z : 0.2f * sc.z;
        sc.w = elv.w + er4.w + wb; sc.w = sc.w > 0.f ? sc.w : 0.2f * sc.w;
        *(float4*)&g_att[p * 4] = sc;
        mx.x = fmaxf(mx.x, sc.x); mx.y = fmaxf(mx.y, sc.y);
        mx.z = fmaxf(mx.z, sc.z); mx.w = fmaxf(mx.w, sc.w);
    }
#pragma unroll
    for (int off = 16; off > 0; off >>= 1) {
        mx.x = fmaxf(mx.x, __shfl_xor_sync(0xffffffffu, mx.x, off));
        mx.y = fmaxf(mx.y, __shfl_xor_sync(0xffffffffu, mx.y, off));
        mx.z = fmaxf(mx.z, __shfl_xor_sync(0xffffffffu, mx.z, off));
        mx.w = fmaxf(mx.w, __shfl_xor_sync(0xffffffffu, mx.w, off));
    }

    float4 sm = make_float4(0.f, 0.f, 0.f, 0.f);
    for (int j = lane; j < deg; j += 32) {
        int p = st + j;
        float4 v = *(const float4*)&g_att[p * 4];
        v.x = __expf(v.x - mx.x); v.y = __expf(v.y - mx.y);
        v.z = __expf(v.z - mx.z); v.w = __expf(v.w - mx.w);
        *(float4*)&g_att[p * 4] = v;
        sm.x += v.x; sm.y += v.y; sm.z += v.z; sm.w += v.w;
    }
#pragma unroll
    for (int off = 16; off > 0; off >>= 1) {
        sm.x += __shfl_xor_sync(0xffffffffu, sm.x, off);
        sm.y += __shfl_xor_sync(0xffffffffu, sm.y, off);
        sm.z += __shfl_xor_sync(0xffffffffu, sm.z, off);
        sm.w += __shfl_xor_sync(0xffffffffu, sm.w, off);
    }
    int hl = lane >> 3;
    float rh = (hl == 0) ? sm.x : (hl == 1) ? sm.y : (hl == 2) ? sm.z : sm.w;
    rh = 1.f / rh;
    __syncwarp();

    float4 acc = make_float4(0.f, 0.f, 0.f, 0.f);
    for (int j = 0; j < deg; j++) {
        int p = st + j;
        int s = g_csrc[p];
        float a = g_att[p * 4 + hl] * rh;
        float4 f = *(const float4*)&ft[s * 128 + lane * 4];
        acc.x = fmaf(f.x, a, acc.x);
        acc.y = fmaf(f.y, a, acc.y);
        acc.z = fmaf(f.z, a, acc.z);
        acc.w = fmaf(f.w, a, acc.w);
    }
    acc.x = acc.x > 0.f ? acc.x : (__expf(acc.x) - 1.f);
    acc.y = acc.y > 0.f ? acc.y : (__expf(acc.y) - 1.f);
    acc.z = acc.z > 0.f ? acc.z : (__expf(acc.z) - 1.f);
    acc.w = acc.w > 0.f ? acc.w : (__expf(acc.w) - 1.f);
    float s1 = acc.x + acc.y + acc.z + acc.w;
    float s2 = acc.x * acc.x + acc.y * acc.y + acc.z * acc.z + acc.w * acc.w;
#pragma unroll
    for (int off = 16; off > 0; off >>= 1) {
        s1 += __shfl_xor_sync(0xffffffffu, s1, off);
        s2 += __shfl_xor_sync(0xffffffffu, s2, off);
    }
    float mu = s1 * (1.f / 128.f);
    float var = s2 * (1.f / 128.f) - mu * mu;
    float rs = rsqrtf(fmaxf(var, 0.f) + LN_EPS);
    float4 g4 = *(const float4*)&gamma[lane * 4];
    float4 b4 = *(const float4*)&beta[lane * 4];
    float4 r4 = *(const float4*)&resid[w * 128 + lane * 4];
    float4 o;
    o.x = (acc.x - mu) * rs * g4.x + b4.x + r4.x;
    o.y = (acc.y - mu) * rs * g4.y + b4.y + r4.y;
    o.z = (acc.z - mu) * rs * g4.z + b4.z + r4.z;
    o.w = (acc.w - mu) * rs * g4.w + b4.w + r4.w;
    *(float4*)&out[w * 128 + lane * 4] = o;
}

// ---- mega kernel, final layer (H=1, OUT=64), dual output write --------------
__global__ void k_mega1(const float* __restrict__ ft, const float* __restrict__ lam,
                        float* __restrict__ out, float* __restrict__ out2) {
    int w = (blockIdx.x * blockDim.x + threadIdx.x) >> 5;
    int lane = threadIdx.x & 31;
    if (w >= NN) return;
    int deg = g_cnt[w];
    int st = g_off[w];
    float lamv = lam[0];
    float er = g_er[w];

    float mx = -1e30f;
    for (int j = lane; j < deg; j += 32) {
        int p = st + j;
        float sc = g_el[g_csrc[p]] + er + lamv * g_cew[p];
        sc = sc > 0.f ? sc : 0.2f * sc;
        g_att[p] = sc;
        mx = fmaxf(mx, sc);
    }
#pragma unroll
    for (int off = 16; off > 0; off >>= 1)
        mx = fmaxf(mx, __shfl_xor_sync(0xffffffffu, mx, off));

    float sm = 0.f;
    for (int j = lane; j < deg; j += 32) {
        int p = st + j;
        float v = __expf(g_att[p] - mx);
        g_att[p] = v;
        sm += v;
    }
#pragma unroll
    for (int off = 16; off > 0; off >>= 1)
        sm += __shfl_xor_sync(0xffffffffu, sm, off);
    float rinv = 1.f / sm;
    __syncwarp();

    float2 acc = make_float2(0.f, 0.f);
    for (int j = 0; j < deg; j++) {
        int p = st + j;
        int s = g_csrc[p];
        float a = g_att[p] * rinv;
        float2 f = *(const float2*)&ft[s * 64 + lane * 2];
        acc.x = fmaf(f.x, a, acc.x);
        acc.y = fmaf(f.y, a, acc.y);
    }
    *(float2*)&out[w * 64 + lane * 2] = acc;
    if (out2) *(float2*)&out2[w * 64 + lane * 2] = acc;
}

// ------------------------------- launch --------------------------------------
extern "C" void kernel_launch(void* const* d_in, const int* in_sizes, int n_in,
                              void* d_out, int out_size) {
    (void)in_sizes; (void)n_in;
    const float* feat = (const float*)d_in[0];
    const float* ew   = (const float*)d_in[1];
    const int*   src  = (const int*)d_in[2];
    const int*   dst  = (const int*)d_in[3];
    const float* W0   = (const float*)d_in[4];
    const float* al0  = (const float*)d_in[5];
    const float* ar0  = (const float*)d_in[6];
    const float* lam0 = (const float*)d_in[7];
    const float* W1   = (const float*)d_in[8];
    const float* al1  = (const float*)d_in[9];
    const float* ar1  = (const float*)d_in[10];
    const float* lam1 = (const float*)d_in[11];
    const float* W2   = (const float*)d_in[12];
    const float* al2  = (const float*)d_in[13];
    const float* ar2  = (const float*)d_in[14];
    const float* lam2 = (const float*)d_in[15];
    const float* g0   = (const float*)d_in[16];
    const float* b0   = (const float*)d_in[17];
    const float* g1   = (const float*)d_in[18];
    const float* b1   = (const float*)d_in[19];

    float* out = (float*)d_out;
    float* out2 = (out_size >= 2 * NN * OUTD) ? out + NN * OUTD : nullptr;

    float *ftp = nullptr, *h1p = nullptr, *h2p = nullptr;
    cudaGetSymbolAddress((void**)&ftp, g_ft);
    cudaGetSymbolAddress((void**)&h1p, g_h1);
    cudaGetSymbolAddress((void**)&h2p, g_h2);

    const int eb = (EE + 255) / 256;
    const int nb512 = (NN + 511) / 512;
    const int nwb = (NN + 7) / 8;
    const int g128b = (NN + 63) / 64;    // MC=128 -> BM=64
    const int g64b = (NN + 127) / 128;   // MC=64  -> BM=128

    // CSR by dst
    k_zero_cnt<<<(NN + 255) / 256, 256>>>();
    k_hist<<<eb, 256>>>(dst);
    k_scan1<<<nb512, 512>>>();
    k_scan2<<<1, 128>>>(nb512);
    k_scan3<<<nb512, 512>>>();
    k_scatter<<<eb, 256>>>(src, dst, ew);

    // layer 0
    k_gemm_tf32<128><<<g128b, 256>>>(feat, W0, ftp);
    k_elr<4, 32><<<nwb, 256>>>(ftp, al0, ar0);
    k_mega4<<<nwb, 256>>>(ftp, lam0, feat, g0, b0, h1p);

    // layer 1
    k_gemm_tf32<128><<<g128b, 256>>>(h1p, W1, ftp);
    k_elr<4, 32><<<nwb, 256>>>(ftp, al1, ar1);
    k_mega4<<<nwb, 256>>>(ftp, lam1, h1p, g1, b1, h2p);

    // layer 2
    k_gemm_tf32<64><<<g64b, 256>>>(h2p, W2, ftp);
    k_elr<1, 64><<<nwb, 256>>>(ftp, al2, ar2);
    k_mega1<<<nwb, 256>>>(ftp, lam2, out, out2);
}

// round 4
// speedup vs baseline: 2.8610x; 1.0148x over previous
#include <cuda_runtime.h>
#include <cstdint>

#define NN   50000
#define EE   800000
#define HD   128
#define OUTD 64
#define LN_EPS 1e-5f

// -------- device scratch --------
__device__ __align__(16) float g_ft[NN * HD];
__device__ __align__(16) float g_h1[NN * HD];
__device__ __align__(16) float g_h2[NN * HD];
__device__ __align__(16) float g_el[NN * 4];
__device__ __align__(16) float g_er[NN * 4];
__device__ __align__(16) float g_att[EE * 4];   // fallback only (deg > 128)
__device__ __align__(16) float g_cew[EE];       // edge weight, CSR order
__device__ int g_csrc[EE];                      // src node, CSR order
__device__ int g_rank[EE];                      // per-edge rank within dst segment
__device__ int g_cnt[NN];
__device__ int g_off[NN];
__device__ int g_bsum[128];

// ---------------------------- CSR build ------------------------------------
__global__ void k_zero_cnt() {
    int i = blockIdx.x * blockDim.x + threadIdx.x;
    if (i < NN) g_cnt[i] = 0;
}

__global__ void k_hist(const int* __restrict__ dst) {
    int e = blockIdx.x * blockDim.x + threadIdx.x;
    if (e < EE) g_rank[e] = atomicAdd(&g_cnt[dst[e]], 1);
}

__global__ void k_scan1() {
    __shared__ int sh[512];
    int t = threadIdx.x;
    int i = blockIdx.x * 512 + t;
    int v = (i < NN) ? g_cnt[i] : 0;
    sh[t] = v;
    __syncthreads();
    for (int off = 1; off < 512; off <<= 1) {
        int add = (t >= off) ? sh[t - off] : 0;
        __syncthreads();
        sh[t] += add;
        __syncthreads();
    }
    if (i < NN) g_off[i] = sh[t];          // inclusive (temp)
    if (t == 511) g_bsum[blockIdx.x] = sh[511];
}

__global__ void k_scan2(int nb) {
    __shared__ int sh[128];
    int t = threadIdx.x;
    int v = (t < nb) ? g_bsum[t] : 0;
    sh[t] = v;
    __syncthreads();
    for (int off = 1; off < 128; off <<= 1) {
        int add = (t >= off) ? sh[t - off] : 0;
        __syncthreads();
        sh[t] += add;
        __syncthreads();
    }
    if (t < nb) g_bsum[t] = sh[t] - v;     // exclusive
}

__global__ void k_scan3() {
    int t = threadIdx.x;
    int i = blockIdx.x * 512 + t;
    if (i < NN) g_off[i] = g_off[i] - g_cnt[i] + g_bsum[blockIdx.x];
}

__global__ void k_scatter(const int* __restrict__ src, const int* __restrict__ dst,
                          const float* __restrict__ ew) {
    int e = blockIdx.x * blockDim.x + threadIdx.x;
    if (e < EE) {
        int p = g_off[dst[e]] + g_rank[e];
        g_csrc[p] = src[e];
        g_cew[p] = ew[e];
    }
}

// --------------------------- tf32 helpers ------------------------------------
__device__ __forceinline__ uint32_t f2tf32(float x) {
    uint32_t r;
    asm("cvt.rna.tf32.f32 %0, %1;" : "=r"(r) : "f"(x));
    return r;
}

// --------------------- tf32 tensor-core GEMM ---------------------------------
template <int MC>
__global__ void k_gemm_tf32(const float* __restrict__ A, const float* __restrict__ B,
                            float* __restrict__ C) {
    constexpr int BM = (MC == 128) ? 64 : 128;
    constexpr int BSTR = MC + 8;
    constexpr int WCOLS = MC / 64;
    constexpr int WROWS = 8 / WCOLS;
    __shared__ uint32_t As[BM][36];
    __shared__ uint32_t Bs[32][BSTR];

    int tid = threadIdx.x;
    int wid = tid >> 5, lane = tid & 31;
    int wr = wid % WROWS, wc = wid / WROWS;
    int row0 = blockIdx.x * BM;

    float c[8][4];
#pragma unroll
    for (int t = 0; t < 8; t++)
#pragma unroll
        for (int i = 0; i < 4; i++) c[t][i] = 0.f;

    for (int kt = 0; kt < 128; kt += 32) {
#pragma unroll
        for (int i = 0; i < BM / 32; i++) {
            int idx = tid + i * 256;
            int r = idx >> 3, cc = idx & 7;
            int gr = row0 + r;
            float4 v = make_float4(0.f, 0.f, 0.f, 0.f);
            if (gr < NN) v = *(const float4*)&A[gr * 128 + kt + cc * 4];
            As[r][cc * 4 + 0] = f2tf32(v.x);
            As[r][cc * 4 + 1] = f2tf32(v.y);
            As[r][cc * 4 + 2] = f2tf32(v.z);
            As[r][cc * 4 + 3] = f2tf32(v.w);
        }
#pragma unroll
        for (int i = 0; i < MC / 32; i++) {
            int idx = tid + i * 256;
            int r = idx / (MC / 4), cc = idx % (MC / 4);
            float4 v = *(const float4*)&B[(kt + r) * MC + cc * 4];
            Bs[r][cc * 4 + 0] = f2tf32(v.x);
            Bs[r][cc * 4 + 1] = f2tf32(v.y);
            Bs[r][cc * 4 + 2] = f2tf32(v.z);
            Bs[r][cc * 4 + 3] = f2tf32(v.w);
        }
        __syncthreads();
#pragma unroll
        for (int ks = 0; ks < 4; ks++) {
            int k0 = ks * 8;
            int ar = wr * 16 + (lane >> 2);
            int ac = k0 + (lane & 3);
            uint32_t a0 = As[ar][ac];
            uint32_t a1 = As[ar + 8][ac];
            uint32_t a2 = As[ar][ac + 4];
            uint32_t a3 = As[ar + 8][ac + 4];
#pragma unroll
            for (int t = 0; t < 8; t++) {
                int n0 = wc * 64 + t * 8 + (lane >> 2);
                uint32_t b0 = Bs[k0 + (lane & 3)][n0];
                uint32_t b1 = Bs[k0 + (lane & 3) + 4][n0];
                asm volatile(
                    "mma.sync.aligned.m16n8k8.row.col.f32.tf32.tf32.f32 "
                    "{%0,%1,%2,%3}, {%4,%5,%6,%7}, {%8,%9}, {%0,%1,%2,%3};"
                    : "+f"(c[t][0]), "+f"(c[t][1]), "+f"(c[t][2]), "+f"(c[t][3])
                    : "r"(a0), "r"(a1), "r"(a2), "r"(a3), "r"(b0), "r"(b1));
            }
        }
        __syncthreads();
    }
    int rbase = row0 + wr * 16 + (lane >> 2);
#pragma unroll
    for (int t = 0; t < 8; t++) {
        int n0 = wc * 64 + t * 8 + 2 * (lane & 3);
        if (rbase < NN)
            *(float2*)&C[rbase * MC + n0] = make_float2(c[t][0], c[t][1]);
        if (rbase + 8 < NN)
            *(float2*)&C[(rbase + 8) * MC + n0] = make_float2(c[t][2], c[t][3]);
    }
}

// --------------------- el/er projections (warp per node) ---------------------
template <int H_, int D_>
__global__ void k_elr(const float* __restrict__ ft, const float* __restrict__ al,
                      const float* __restrict__ ar) {
    constexpr int VEC = H_ * D_ / 32;
    constexpr int GROUP = 32 / H_;
    int w = (blockIdx.x * blockDim.x + threadIdx.x) >> 5;
    int lane = threadIdx.x & 31;
    if (w >= NN) return;
    const float* f = ft + w * (H_ * D_) + lane * VEC;
    float dl = 0.f, dr = 0.f;
#pragma unroll
    for (int v = 0; v < VEC; v++) {
        float x = f[v];
        dl = fmaf(x, al[lane * VEC + v], dl);
        dr = fmaf(x, ar[lane * VEC + v], dr);
    }
#pragma unroll
    for (int off = GROUP / 2; off > 0; off >>= 1) {
        dl += __shfl_xor_sync(0xffffffffu, dl, off);
        dr += __shfl_xor_sync(0xffffffffu, dr, off);
    }
    if ((lane & (GROUP - 1)) == 0) {
        int h = lane / GROUP;
        g_el[w * H_ + h] = dl;
        g_er[w * H_ + h] = dr;
    }
}

__device__ __forceinline__ float4 lrelu4(float4 v) {
    v.x = v.x > 0.f ? v.x : 0.2f * v.x;
    v.y = v.y > 0.f ? v.y : 0.2f * v.y;
    v.z = v.z > 0.f ? v.z : 0.2f * v.z;
    v.w = v.w > 0.f ? v.w : 0.2f * v.w;
    return v;
}

// ---- mega kernel, hidden layers (H=4,D=32) ----------------------------------
__global__ void k_mega4(const float* __restrict__ ft, const float* __restrict__ lam,
                        const float* __restrict__ resid, const float* __restrict__ gamma,
                        const float* __restrict__ beta, float* __restrict__ out) {
    __shared__ float s_att[8][512];
    __shared__ int s_src[8][128];
    int wslot = threadIdx.x >> 5;
    int w = (blockIdx.x * blockDim.x + threadIdx.x) >> 5;
    int lane = threadIdx.x & 31;
    if (w >= NN) return;
    int deg = g_cnt[w];
    int st = g_off[w];
    float lamv = lam[0];
    float4 er4 = *(const float4*)&g_er[w * 4];
    int hl = lane >> 3;

    float4 acc = make_float4(0.f, 0.f, 0.f, 0.f);

    if (deg <= 128) {
        // ---------- register-resident softmax ----------
        float4 sc[4];
        float4 mx = make_float4(-1e30f, -1e30f, -1e30f, -1e30f);
#pragma unroll
        for (int k = 0; k < 4; k++) {
            int j = lane + 32 * k;
            if (j < deg) {
                int p = st + j;
                int s = g_csrc[p];
                s_src[wslot][j] = s;
                float wb = lamv * g_cew[p];
                float4 elv = *(const float4*)&g_el[s * 4];
                float4 v;
                v.x = elv.x + er4.x + wb; v.y = elv.y + er4.y + wb;
                v.z = elv.z + er4.z + wb; v.w = elv.w + er4.w + wb;
                v = lrelu4(v);
                sc[k] = v;
                mx.x = fmaxf(mx.x, v.x); mx.y = fmaxf(mx.y, v.y);
                mx.z = fmaxf(mx.z, v.z); mx.w = fmaxf(mx.w, v.w);
            }
        }
#pragma unroll
        for (int off = 16; off > 0; off >>= 1) {
            mx.x = fmaxf(mx.x, __shfl_xor_sync(0xffffffffu, mx.x, off));
            mx.y = fmaxf(mx.y, __shfl_xor_sync(0xffffffffu, mx.y, off));
            mx.z = fmaxf(mx.z, __shfl_xor_sync(0xffffffffu, mx.z, off));
            mx.w = fmaxf(mx.w, __shfl_xor_sync(0xffffffffu, mx.w, off));
        }
        float4 sm = make_float4(0.f, 0.f, 0.f, 0.f);
#pragma unroll
        for (int k = 0; k < 4; k++) {
            int j = lane + 32 * k;
            if (j < deg) {
                sc[k].x = __expf(sc[k].x - mx.x);
                sc[k].y = __expf(sc[k].y - mx.y);
                sc[k].z = __expf(sc[k].z - mx.z);
                sc[k].w = __expf(sc[k].w - mx.w);
                sm.x += sc[k].x; sm.y += sc[k].y; sm.z += sc[k].z; sm.w += sc[k].w;
            }
        }
#pragma unroll
        for (int off = 16; off > 0; off >>= 1) {
            sm.x += __shfl_xor_sync(0xffffffffu, sm.x, off);
            sm.y += __shfl_xor_sync(0xffffffffu, sm.y, off);
            sm.z += __shfl_xor_sync(0xffffffffu, sm.z, off);
            sm.w += __shfl_xor_sync(0xffffffffu, sm.w, off);
        }
        float rh = (hl == 0) ? sm.x : (hl == 1) ? sm.y : (hl == 2) ? sm.z : sm.w;
        float rinv = 1.f / rh;
#pragma unroll
        for (int k = 0; k < 4; k++) {
            int j = lane + 32 * k;
            if (j < deg) *(float4*)&s_att[wslot][j * 4] = sc[k];
        }
        __syncwarp();
        // ---------- aggregate ----------
#pragma unroll 2
        for (int j = 0; j < deg; j++) {
            float a = s_att[wslot][j * 4 + hl] * rinv;
            int s = s_src[wslot][j];
            float4 f = *(const float4*)&ft[s * 128 + lane * 4];
            acc.x = fmaf(f.x, a, acc.x);
            acc.y = fmaf(f.y, a, acc.y);
            acc.z = fmaf(f.z, a, acc.z);
            acc.w = fmaf(f.w, a, acc.w);
        }
    } else {
        // ---------- fallback: global-memory path ----------
        float4 mx = make_float4(-1e30f, -1e30f, -1e30f, -1e30f);
        for (int j = lane; j < deg; j += 32) {
            int p = st + j;
            int s = g_csrc[p];
            float wb = lamv * g_cew[p];
            float4 elv = *(const float4*)&g_el[s * 4];
            float4 v;
            v.x = elv.x + er4.x + wb; v.y = elv.y + er4.y + wb;
            v.z = elv.z + er4.z + wb; v.w = elv.w + er4.w + wb;
            v = lrelu4(v);
            *(float4*)&g_att[p * 4] = v;
            mx.x = fmaxf(mx.x, v.x); mx.y = fmaxf(mx.y, v.y);
            mx.z = fmaxf(mx.z, v.z); mx.w = fmaxf(mx.w, v.w);
        }
#pragma unroll
        for (int off = 16; off > 0; off >>= 1) {
            mx.x = fmaxf(mx.x, __shfl_xor_sync(0xffffffffu, mx.x, off));
            mx.y = fmaxf(mx.y, __shfl_xor_sync(0xffffffffu, mx.y, off));
            mx.z = fmaxf(mx.z, __shfl_xor_sync(0xffffffffu, mx.z, off));
            mx.w = fmaxf(mx.w, __shfl_xor_sync(0xffffffffu, mx.w, off));
        }
        float4 sm = make_float4(0.f, 0.f, 0.f, 0.f);
        for (int j = lane; j < deg; j += 32) {
            int p = st + j;
            float4 v = *(const float4*)&g_att[p * 4];
            v.x = __expf(v.x - mx.x); v.y = __expf(v.y - mx.y);
            v.z = __expf(v.z - mx.z); v.w = __expf(v.w - mx.w);
            *(float4*)&g_att[p * 4] = v;
            sm.x += v.x; sm.y += v.y; sm.z += v.z; sm.w += v.w;
        }
#pragma unroll
        for (int off = 16; off > 0; off >>= 1) {
            sm.x += __shfl_xor_sync(0xffffffffu, sm.x, off);
            sm.y += __shfl_xor_sync(0xffffffffu, sm.y, off);
            sm.z += __shfl_xor_sync(0xffffffffu, sm.z, off);
            sm.w += __shfl_xor_sync(0xffffffffu, sm.w, off);
        }
        float rh = (hl == 0) ? sm.x : (hl == 1) ? sm.y : (hl == 2) ? sm.z : sm.w;
        float rinv = 1.f / rh;
        __syncwarp();
        for (int j = 0; j < deg; j++) {
            int p = st + j;
            int s = g_csrc[p];
            float a = g_att[p * 4 + hl] * rinv;
            float4 f = *(const float4*)&ft[s * 128 + lane * 4];
            acc.x = fmaf(f.x, a, acc.x);
            acc.y = fmaf(f.y, a, acc.y);
            acc.z = fmaf(f.z, a, acc.z);
            acc.w = fmaf(f.w, a, acc.w);
        }
    }

    // ---------- ELU + LayerNorm + residual ----------
    acc.x = acc.x > 0.f ? acc.x : (__expf(acc.x) - 1.f);
    acc.y = acc.y > 0.f ? acc.y : (__expf(acc.y) - 1.f);
    acc.z = acc.z > 0.f ? acc.z : (__expf(acc.z) - 1.f);
    acc.w = acc.w > 0.f ? acc.w : (__expf(acc.w) - 1.f);
    float s1 = acc.x + acc.y + acc.z + acc.w;
    float s2 = acc.x * acc.x + acc.y * acc.y + acc.z * acc.z + acc.w * acc.w;
#pragma unroll
    for (int off = 16; off > 0; off >>= 1) {
        s1 += __shfl_xor_sync(0xffffffffu, s1, off);
        s2 += __shfl_xor_sync(0xffffffffu, s2, off);
    }
    float mu = s1 * (1.f / 128.f);
    float var = s2 * (1.f / 128.f) - mu * mu;
    float rs = rsqrtf(fmaxf(var, 0.f) + LN_EPS);
    float4 g4 = *(const float4*)&gamma[lane * 4];
    float4 b4 = *(const float4*)&beta[lane * 4];
    float4 r4 = *(const float4*)&resid[w * 128 + lane * 4];
    float4 o;
    o.x = (acc.x - mu) * rs * g4.x + b4.x + r4.x;
    o.y = (acc.y - mu) * rs * g4.y + b4.y + r4.y;
    o.z = (acc.z - mu) * rs * g4.z + b4.z + r4.z;
    o.w = (acc.w - mu) * rs * g4.w + b4.w + r4.w;
    *(float4*)&out[w * 128 + lane * 4] = o;
}

// ---- mega kernel, final layer (H=1, OUT=64) ---------------------------------
__global__ void k_mega1(const float* __restrict__ ft, const float* __restrict__ lam,
                        float* __restrict__ out, float* __restrict__ out2) {
    __shared__ float s_att[8][128];
    __shared__ int s_src[8][128];
    int wslot = threadIdx.x >> 5;
    int w = (blockIdx.x * blockDim.x + threadIdx.x) >> 5;
    int lane = threadIdx.x & 31;
    if (w >= NN) return;
    int deg = g_cnt[w];
    int st = g_off[w];
    float lamv = lam[0];
    float er = g_er[w];

    float2 acc = make_float2(0.f, 0.f);

    if (deg <= 128) {
        float sc[4];
        float mx = -1e30f;
#pragma unroll
        for (int k = 0; k < 4; k++) {
            int j = lane + 32 * k;
            if (j < deg) {
                int p = st + j;
                int s = g_csrc[p];
                s_src[wslot][j] = s;
                float v = g_el[s] + er + lamv * g_cew[p];
                v = v > 0.f ? v : 0.2f * v;
                sc[k] = v;
                mx = fmaxf(mx, v);
            }
        }
#pragma unroll
        for (int off = 16; off > 0; off >>= 1)
            mx = fmaxf(mx, __shfl_xor_sync(0xffffffffu, mx, off));
        float sm = 0.f;
#pragma unroll
        for (int k = 0; k < 4; k++) {
            int j = lane + 32 * k;
            if (j < deg) { sc[k] = __expf(sc[k] - mx); sm += sc[k]; }
        }
#pragma unroll
        for (int off = 16; off > 0; off >>= 1)
            sm += __shfl_xor_sync(0xffffffffu, sm, off);
        float rinv = 1.f / sm;
#pragma unroll
        for (int k = 0; k < 4; k++) {
            int j = lane + 32 * k;
            if (j < deg) s_att[wslot][j] = sc[k];
        }
        __syncwarp();
#pragma unroll 2
        for (int j = 0; j < deg; j++) {
            float a = s_att[wslot][j] * rinv;
            int s = s_src[wslot][j];
            float2 f = *(const float2*)&ft[s * 64 + lane * 2];
            acc.x = fmaf(f.x, a, acc.x);
            acc.y = fmaf(f.y, a, acc.y);
        }
    } else {
        float mx = -1e30f;
        for (int j = lane; j < deg; j += 32) {
            int p = st + j;
            float v = g_el[g_csrc[p]] + er + lamv * g_cew[p];
            v = v > 0.f ? v : 0.2f * v;
            g_att[p] = v;
            mx = fmaxf(mx, v);
        }
#pragma unroll
        for (int off = 16; off > 0; off >>= 1)
            mx = fmaxf(mx, __shfl_xor_sync(0xffffffffu, mx, off));
        float sm = 0.f;
        for (int j = lane; j < deg; j += 32) {
            int p = st + j;
            float v = __expf(g_att[p] - mx);
            g_att[p] = v;
            sm += v;
        }
#pragma unroll
        for (int off = 16; off > 0; off >>= 1)
            sm += __shfl_xor_sync(0xffffffffu, sm, off);
        float rinv = 1.f / sm;
        __syncwarp();
        for (int j = 0; j < deg; j++) {
            int p = st + j;
            int s = g_csrc[p];
            float a = g_att[p] * rinv;
            float2 f = *(const float2*)&ft[s * 64 + lane * 2];
            acc.x = fmaf(f.x, a, acc.x);
            acc.y = fmaf(f.y, a, acc.y);
        }
    }
    *(float2*)&out[w * 64 + lane * 2] = acc;
    if (out2) *(float2*)&out2[w * 64 + lane * 2] = acc;
}

// ------------------------------- launch --------------------------------------
extern "C" void kernel_launch(void* const* d_in, const int* in_sizes, int n_in,
                              void* d_out, int out_size) {
    (void)in_sizes; (void)n_in;
    const float* feat = (const float*)d_in[0];
    const float* ew   = (const float*)d_in[1];
    const int*   src  = (const int*)d_in[2];
    const int*   dst  = (const int*)d_in[3];
    const float* W0   = (const float*)d_in[4];
    const float* al0  = (const float*)d_in[5];
    const float* ar0  = (const float*)d_in[6];
    const float* lam0 = (const float*)d_in[7];
    const float* W1   = (const float*)d_in[8];
    const float* al1  = (const float*)d_in[9];
    const float* ar1  = (const float*)d_in[10];
    const float* lam1 = (const float*)d_in[11];
    const float* W2   = (const float*)d_in[12];
    const float* al2  = (const float*)d_in[13];
    const float* ar2  = (const float*)d_in[14];
    const float* lam2 = (const float*)d_in[15];
    const float* g0   = (const float*)d_in[16];
    const float* b0   = (const float*)d_in[17];
    const float* g1   = (const float*)d_in[18];
    const float* b1   = (const float*)d_in[19];

    float* out = (float*)d_out;
    float* out2 = (out_size >= 2 * NN * OUTD) ? out + NN * OUTD : nullptr;

    float *ftp = nullptr, *h1p = nullptr, *h2p = nullptr;
    cudaGetSymbolAddress((void**)&ftp, g_ft);
    cudaGetSymbolAddress((void**)&h1p, g_h1);
    cudaGetSymbolAddress((void**)&h2p, g_h2);

    const int eb = (EE + 255) / 256;
    const int nb512 = (NN + 511) / 512;
    const int nwb = (NN + 7) / 8;
    const int g128b = (NN + 63) / 64;
    const int g64b = (NN + 127) / 128;

    // CSR by dst (atomic-free scatter via rank)
    k_zero_cnt<<<(NN + 255) / 256, 256>>>();
    k_hist<<<eb, 256>>>(dst);
    k_scan1<<<nb512, 512>>>();
    k_scan2<<<1, 128>>>(nb512);
    k_scan3<<<nb512, 512>>>();
    k_scatter<<<eb, 256>>>(src, dst, ew);

    // layer 0
    k_gemm_tf32<128><<<g128b, 256>>>(feat, W0, ftp);
    k_elr<4, 32><<<nwb, 256>>>(ftp, al0, ar0);
    k_mega4<<<nwb, 256>>>(ftp, lam0, feat, g0, b0, h1p);

    // layer 1
    k_gemm_tf32<128><<<g128b, 256>>>(h1p, W1, ftp);
    k_elr<4, 32><<<nwb, 256>>>(ftp, al1, ar1);
    k_mega4<<<nwb, 256>>>(ftp, lam1, h1p, g1, b1, h2p);

    // layer 2
    k_gemm_tf32<64><<<g64b, 256>>>(h2p, W2, ftp);
    k_elr<1, 64><<<nwb, 256>>>(ftp, al2, ar2);
    k_mega1<<<nwb, 256>>>(ftp, lam2, out, out2);
}